// round 2
// baseline (speedup 1.0000x reference)
#include <cuda_runtime.h>
#include <cooperative_groups.h>
namespace cg = cooperative_groups;

#define SEQ   2048
#define INDIM 256
#define HID   256
#define G3    768

// Precomputed input projection gx[b][t][768] (includes bx). ~805 MB scratch.
__device__ float g_gx[(size_t)128 * SEQ * G3];

// ---- f32x2 packed helpers (SASS FFMA2 path, PTX-only) ----------------------
static __device__ __forceinline__ unsigned long long dup2(float a) {
    unsigned long long r;
    asm("mov.b64 %0, {%1, %1};" : "=l"(r) : "f"(a));
    return r;
}
static __device__ __forceinline__ void fma2(unsigned long long& d,
                                            unsigned long long a,
                                            unsigned long long b) {
    asm("fma.rn.f32x2 %0, %1, %2, %0;" : "+l"(d) : "l"(a), "l"(b));
}
static __device__ __forceinline__ float2 unp2(unsigned long long v) {
    float2 r;
    asm("mov.b64 {%0, %1}, %2;" : "=f"(r.x), "=f"(r.y) : "l"(v));
    return r;
}

// ---------------------------------------------------------------------------
// Phase 1: gx = x @ Wx^T + bx.  Rows m = b*SEQ + t (contiguous), cols n<768.
// BM=128, BN=64, full K=256 single pass. 256 threads, 8x4 microtile, f32x2.
// ---------------------------------------------------------------------------
#define GM 128
#define GN 64
#define APAD 132
#define BPAD 68
#define GX_SMEM ((256 * APAD + 256 * BPAD) * 4)   // 204800 B

__global__ void __launch_bounds__(256, 1)
gx_gemm(const float* __restrict__ x, const float* __restrict__ Wx,
        const float* __restrict__ bx) {
    extern __shared__ float sm[];
    float* As = sm;                 // As[k][m], k<256, m<128
    float* Bs = sm + 256 * APAD;    // Bs[k][n], n<64

    const int bid = blockIdx.x;
    const int mt = bid / (G3 / GN);
    const int nt = bid % (G3 / GN);
    const long m0 = (long)mt * GM;
    const int  n0 = nt * GN;
    const int tid = threadIdx.x;

    {   // A tile: 128 rows x 256 floats (contiguous block of x)
        const float4* src = (const float4*)(x + m0 * INDIM);
        for (int i = tid; i < GM * (INDIM / 4); i += 256) {
            float4 v = src[i];
            int m = i >> 6;
            int k = (i & 63) << 2;
            As[(k + 0) * APAD + m] = v.x;
            As[(k + 1) * APAD + m] = v.y;
            As[(k + 2) * APAD + m] = v.z;
            As[(k + 3) * APAD + m] = v.w;
        }
    }
    {   // B tile: Wx rows n0..n0+63, transposed into Bs[k][n]
        const float4* src = (const float4*)(Wx + (long)n0 * INDIM);
        for (int i = tid; i < GN * (INDIM / 4); i += 256) {
            float4 v = src[i];
            int n = i >> 6;
            int k = (i & 63) << 2;
            Bs[(k + 0) * BPAD + n] = v.x;
            Bs[(k + 1) * BPAD + n] = v.y;
            Bs[(k + 2) * BPAD + n] = v.z;
            Bs[(k + 3) * BPAD + n] = v.w;
        }
    }
    __syncthreads();

    const int tm = (tid & 15) * 8;
    const int tn = (tid >> 4) * 4;

    unsigned long long acc[8][2];
#pragma unroll
    for (int i = 0; i < 8; i++) { acc[i][0] = 0ull; acc[i][1] = 0ull; }

#pragma unroll 8
    for (int k = 0; k < INDIM; k++) {
        float4 a0 = *(const float4*)&As[k * APAD + tm];
        float4 a1 = *(const float4*)&As[k * APAD + tm + 4];
        ulonglong2 bv = *(const ulonglong2*)&Bs[k * BPAD + tn];
        float am[8] = {a0.x, a0.y, a0.z, a0.w, a1.x, a1.y, a1.z, a1.w};
#pragma unroll
        for (int i = 0; i < 8; i++) {
            unsigned long long ad = dup2(am[i]);
            fma2(acc[i][0], ad, bv.x);
            fma2(acc[i][1], ad, bv.y);
        }
    }

    const float b0 = bx[n0 + tn + 0], b1 = bx[n0 + tn + 1];
    const float b2 = bx[n0 + tn + 2], b3 = bx[n0 + tn + 3];
#pragma unroll
    for (int i = 0; i < 8; i++) {
        float2 lo = unp2(acc[i][0]);
        float2 hi = unp2(acc[i][1]);
        float4 o;
        o.x = lo.x + b0; o.y = lo.y + b1; o.z = hi.x + b2; o.w = hi.y + b3;
        *(float4*)&g_gx[(m0 + tm + i) * G3 + n0 + tn] = o;
    }
}

// ---------------------------------------------------------------------------
// Phase 2: persistent recurrence. 32 clusters x 4 CTAs, 384 threads.
// Cluster cl owns batches [4cl, 4cl+4). CTA rank r owns hidden units
// [64r, 64r+64) => gate rows {u, 256+u, 512+u}. Wh slice (192x256) resident
// in smem; h (4 batches x 256) replicated per CTA, double buffered; h_new
// broadcast via DSMEM; one cluster.sync per step.
// ---------------------------------------------------------------------------
#define CLUSTER 4
#define UB   64
#define ROWS 192
#define BPC  4
#define NTHR 384
#define WPAD 257

#define OFF_H    (ROWS * WPAD)                 // 49344
#define OFF_P    (OFF_H + 2 * HID * BPC)       // +2048
#define OFF_BH   (OFF_P + 2 * ROWS * BPC)      // +1536
#define REC_SMEM ((OFF_BH + ROWS) * 4)         // 212480 B

__global__ void __launch_bounds__(NTHR, 1) __cluster_dims__(CLUSTER, 1, 1)
gru_rec(const float* __restrict__ Wh, const float* __restrict__ bh,
        const float* __restrict__ Wfc, const float* __restrict__ bfc,
        float* __restrict__ out) {
    extern __shared__ float sm[];
    float* ws   = sm;            // ws[j][k], j<192 (gate row), k<256
    float* hbuf = sm + OFF_H;    // hbuf[buf][k][b]: 2 x 256 x 4
    float* part = sm + OFF_P;    // part[c*192+j][b]
    float* bhs  = sm + OFF_BH;   // bh slice

    cg::cluster_group cl = cg::this_cluster();
    const int rank = (int)cl.block_rank();
    const int clid = (int)blockIdx.x / CLUSTER;
    const int tid  = threadIdx.x;
    const int U0   = rank * UB;
    const int B0   = clid * BPC;

    // Load Wh slice: local row j -> global gate row (j/64)*256 + U0 + (j%64)
    for (int e4 = tid; e4 < ROWS * (HID / 4); e4 += NTHR) {
        int j = e4 >> 6;
        int k = (e4 & 63) << 2;
        int grow = (j / UB) * HID + U0 + (j % UB);
        float4 v = *(const float4*)&Wh[(long)grow * HID + k];
        ws[j * WPAD + k + 0] = v.x;
        ws[j * WPAD + k + 1] = v.y;
        ws[j * WPAD + k + 2] = v.z;
        ws[j * WPAD + k + 3] = v.w;
    }
    for (int j = tid; j < ROWS; j += NTHR)
        bhs[j] = bh[(j / UB) * HID + U0 + (j % UB)];
    for (int i = tid; i < 2 * HID * BPC; i += NTHR)
        hbuf[i] = 0.0f;
    __syncthreads();
    cl.sync();

    const int c = tid / ROWS;           // k-half
    const int j = tid % ROWS;           // gate row
    const float* wrow = ws + j * WPAD + c * 128;
    const int gu = tid & 63;            // gate-phase unit  (tid < 256)
    const int gb = tid >> 6;            // gate-phase batch (tid < 256)

    // Pre-resolve peer hbuf pointers
    float* peer[CLUSTER];
#pragma unroll
    for (int r = 0; r < CLUSTER; r++)
        peer[r] = (float*)cl.map_shared_rank(hbuf, r);

    for (int t = 0; t < SEQ; t++) {
        const int cur = t & 1;
        const int nxt = cur ^ 1;

        // Prefetch gx for this (batch, t, unit) — hidden under the dot loop
        float gxr = 0.f, gxz = 0.f, gxn = 0.f;
        if (tid < 256) {
            const float* gp = g_gx + ((long)(B0 + gb) * SEQ + t) * G3 + (U0 + gu);
            gxr = gp[0]; gxz = gp[256]; gxn = gp[512];
        }

        // Partial dots over this thread's 128-long k-half, 4 batches at once
        const float4* hv = (const float4*)(hbuf + cur * HID * BPC) + c * 128;
        float a0 = 0.f, a1 = 0.f, a2 = 0.f, a3 = 0.f;
#pragma unroll 8
        for (int k = 0; k < 128; k++) {
            float w = wrow[k];
            float4 hh = hv[k];     // broadcast across warp
            a0 += w * hh.x; a1 += w * hh.y; a2 += w * hh.z; a3 += w * hh.w;
        }
        float* pp = part + (c * ROWS + j) * BPC;
        pp[0] = a0; pp[1] = a1; pp[2] = a2; pp[3] = a3;
        __syncthreads();

        if (tid < 256) {
            float sr = part[(gu)       * BPC + gb] + part[(ROWS + gu)       * BPC + gb] + bhs[gu];
            float sz = part[(64 + gu)  * BPC + gb] + part[(ROWS + 64 + gu)  * BPC + gb] + bhs[64 + gu];
            float sn = part[(128 + gu) * BPC + gb] + part[(ROWS + 128 + gu) * BPC + gb] + bhs[128 + gu];
            float r = 1.0f / (1.0f + __expf(-(gxr + sr)));
            float z = 1.0f / (1.0f + __expf(-(gxz + sz)));
            float narg = gxn + r * sn;
            float n = 2.0f / (1.0f + __expf(-2.0f * narg)) - 1.0f;  // tanh
            float hold = hbuf[cur * HID * BPC + (U0 + gu) * BPC + gb];
            float hnew = n + z * (hold - n);
            int off = nxt * HID * BPC + (U0 + gu) * BPC + gb;
#pragma unroll
            for (int r2 = 0; r2 < CLUSTER; r2++)
                peer[r2][off] = hnew;
        }
        cl.sync();   // release DSMEM stores; full cluster+CTA barrier
    }

    // Final h lives in buffer 0 (t=2047: nxt=0). Rank 0 emits out[b][2].
    if (rank == 0) {
        const int w = tid >> 5, lane = tid & 31;
        if (w < 8) {
            const int b = w >> 1, o = w & 1;
            float s = 0.f;
            for (int k = lane; k < HID; k += 32)
                s += hbuf[k * BPC + b] * __ldg(&Wfc[o * HID + k]);
#pragma unroll
            for (int d = 16; d > 0; d >>= 1)
                s += __shfl_xor_sync(0xFFFFFFFFu, s, d);
            if (lane == 0)
                out[(B0 + b) * 2 + o] = s + bfc[o];
        }
    }
}

// ---------------------------------------------------------------------------
extern "C" void kernel_launch(void* const* d_in, const int* in_sizes, int n_in,
                              void* d_out, int out_size) {
    const float* x   = (const float*)d_in[0];
    const float* Wx  = (const float*)d_in[1];
    const float* bx  = (const float*)d_in[2];
    const float* Wh  = (const float*)d_in[3];
    const float* bh  = (const float*)d_in[4];
    const float* Wfc = (const float*)d_in[5];
    const float* bfc = (const float*)d_in[6];
    float* out = (float*)d_out;

    cudaFuncSetAttribute(gx_gemm, cudaFuncAttributeMaxDynamicSharedMemorySize, GX_SMEM);
    cudaFuncSetAttribute(gru_rec, cudaFuncAttributeMaxDynamicSharedMemorySize, REC_SMEM);

    const int mtiles = (128 * SEQ) / GM;     // 2048
    const int ntiles = G3 / GN;              // 12
    gx_gemm<<<mtiles * ntiles, 256, GX_SMEM>>>(x, Wx, bx);
    gru_rec<<<32 * CLUSTER, NTHR, REC_SMEM>>>(Wh, bh, Wfc, bfc, out);
}

// round 3
// speedup vs baseline: 1.2692x; 1.2692x over previous
#include <cuda_runtime.h>
#include <cooperative_groups.h>
namespace cg = cooperative_groups;

#define SEQ   2048
#define INDIM 256
#define HID   256
#define G3    768

// Precomputed input projection gx[b][t][768] (includes bx). ~805 MB scratch.
__device__ float g_gx[(size_t)128 * SEQ * G3];

// ---- f32x2 packed helpers (SASS FFMA2 path, PTX-only) ----------------------
static __device__ __forceinline__ unsigned long long dup2(float a) {
    unsigned long long r;
    asm("mov.b64 %0, {%1, %1};" : "=l"(r) : "f"(a));
    return r;
}
static __device__ __forceinline__ void fma2(unsigned long long& d,
                                            unsigned long long a,
                                            unsigned long long b) {
    asm("fma.rn.f32x2 %0, %1, %2, %0;" : "+l"(d) : "l"(a), "l"(b));
}
static __device__ __forceinline__ float2 unp2(unsigned long long v) {
    float2 r;
    asm("mov.b64 {%0, %1}, %2;" : "=f"(r.x), "=f"(r.y) : "l"(v));
    return r;
}

// ---------------------------------------------------------------------------
// Phase 1: gx = x @ Wx^T + bx.  (unchanged from round 1)
// ---------------------------------------------------------------------------
#define GM 128
#define GN 64
#define APAD 132
#define BPAD 68
#define GX_SMEM ((256 * APAD + 256 * BPAD) * 4)   // 204800 B

__global__ void __launch_bounds__(256, 1)
gx_gemm(const float* __restrict__ x, const float* __restrict__ Wx,
        const float* __restrict__ bx) {
    extern __shared__ float sm[];
    float* As = sm;                 // As[k][m]
    float* Bs = sm + 256 * APAD;    // Bs[k][n]

    const int bid = blockIdx.x;
    const int mt = bid / (G3 / GN);
    const int nt = bid % (G3 / GN);
    const long m0 = (long)mt * GM;
    const int  n0 = nt * GN;
    const int tid = threadIdx.x;

    {
        const float4* src = (const float4*)(x + m0 * INDIM);
        for (int i = tid; i < GM * (INDIM / 4); i += 256) {
            float4 v = src[i];
            int m = i >> 6;
            int k = (i & 63) << 2;
            As[(k + 0) * APAD + m] = v.x;
            As[(k + 1) * APAD + m] = v.y;
            As[(k + 2) * APAD + m] = v.z;
            As[(k + 3) * APAD + m] = v.w;
        }
    }
    {
        const float4* src = (const float4*)(Wx + (long)n0 * INDIM);
        for (int i = tid; i < GN * (INDIM / 4); i += 256) {
            float4 v = src[i];
            int n = i >> 6;
            int k = (i & 63) << 2;
            Bs[(k + 0) * BPAD + n] = v.x;
            Bs[(k + 1) * BPAD + n] = v.y;
            Bs[(k + 2) * BPAD + n] = v.z;
            Bs[(k + 3) * BPAD + n] = v.w;
        }
    }
    __syncthreads();

    const int tm = (tid & 15) * 8;
    const int tn = (tid >> 4) * 4;

    unsigned long long acc[8][2];
#pragma unroll
    for (int i = 0; i < 8; i++) { acc[i][0] = 0ull; acc[i][1] = 0ull; }

#pragma unroll 8
    for (int k = 0; k < INDIM; k++) {
        float4 a0 = *(const float4*)&As[k * APAD + tm];
        float4 a1 = *(const float4*)&As[k * APAD + tm + 4];
        ulonglong2 bv = *(const ulonglong2*)&Bs[k * BPAD + tn];
        float am[8] = {a0.x, a0.y, a0.z, a0.w, a1.x, a1.y, a1.z, a1.w};
#pragma unroll
        for (int i = 0; i < 8; i++) {
            unsigned long long ad = dup2(am[i]);
            fma2(acc[i][0], ad, bv.x);
            fma2(acc[i][1], ad, bv.y);
        }
    }

    const float b0 = bx[n0 + tn + 0], b1 = bx[n0 + tn + 1];
    const float b2 = bx[n0 + tn + 2], b3 = bx[n0 + tn + 3];
#pragma unroll
    for (int i = 0; i < 8; i++) {
        float2 lo = unp2(acc[i][0]);
        float2 hi = unp2(acc[i][1]);
        float4 o;
        o.x = lo.x + b0; o.y = lo.y + b1; o.z = hi.x + b2; o.w = hi.y + b3;
        *(float4*)&g_gx[(m0 + tm + i) * G3 + n0 + tn] = o;
    }
}

// ---------------------------------------------------------------------------
// Phase 2: persistent recurrence v2.
// 32 clusters x 4 CTAs, 768 threads. CTA owns 64 hidden units (192 gate rows).
// Thread (c = tid/96 in 0..7, j = tid%96) computes k-slice [32c,32c+32) for
// rows rA=j (weights in REGISTERS) and rB=j+96 (weights from smem), 4 batches
// batch-packed in f32x2. Partials in smem [b][c*192+r] (stride-1 lanes).
// h broadcast to peers via DSMEM; one cluster.sync per step.
// ---------------------------------------------------------------------------
#define CLUSTER 4
#define UB    64
#define ROWS  192
#define BPC   4
#define NTHR  768
#define WPAD  258
#define NSLC  8
#define KSL   32

#define OFF_H    (ROWS * WPAD)                  // 49536
#define OFF_P    (OFF_H + 2 * HID * BPC)        // +2048
#define OFF_BH   (OFF_P + BPC * NSLC * ROWS)    // +6144
#define REC_SMEM ((OFF_BH + ROWS) * 4)          // 231680 B

__global__ void __launch_bounds__(NTHR, 1) __cluster_dims__(CLUSTER, 1, 1)
gru_rec(const float* __restrict__ Wh, const float* __restrict__ bh,
        const float* __restrict__ Wfc, const float* __restrict__ bfc,
        float* __restrict__ out) {
    extern __shared__ float sm[];
    float* ws   = sm;            // ws[r][k], r<192 local gate row, k<256
    float* hbuf = sm + OFF_H;    // hbuf[buf][k][b]: 2 x 256 x 4
    float* part = sm + OFF_P;    // part[b][c*192 + r]
    float* bhs  = sm + OFF_BH;

    cg::cluster_group cl = cg::this_cluster();
    const int rank = (int)cl.block_rank();
    const int clid = (int)blockIdx.x / CLUSTER;
    const int tid  = threadIdx.x;
    const int U0   = rank * UB;
    const int B0   = clid * BPC;

    // Load Wh slice: local row r -> global gate row (r/64)*256 + U0 + (r%64)
    for (int e4 = tid; e4 < ROWS * (HID / 4); e4 += NTHR) {
        int r = e4 >> 6;
        int k = (e4 & 63) << 2;
        int grow = (r / UB) * HID + U0 + (r % UB);
        float4 v = *(const float4*)&Wh[(long)grow * HID + k];
        ws[r * WPAD + k + 0] = v.x;
        ws[r * WPAD + k + 1] = v.y;
        ws[r * WPAD + k + 2] = v.z;
        ws[r * WPAD + k + 3] = v.w;
    }
    for (int r = tid; r < ROWS; r += NTHR)
        bhs[r] = bh[(r / UB) * HID + U0 + (r % UB)];
    for (int i = tid; i < 2 * HID * BPC; i += NTHR)
        hbuf[i] = 0.0f;
    __syncthreads();

    const int c  = tid / 96;           // k-slice 0..7
    const int j  = tid % 96;
    const int rA = j;
    const int rB = j + 96;
    const float* wsB = ws + rB * WPAD + c * KSL;

    // Row-A weights -> registers (constant indices after full unroll)
    float wa[KSL];
    {
        const float* wsA = ws + rA * WPAD + c * KSL;
#pragma unroll
        for (int k = 0; k < KSL; k++) wa[k] = wsA[k];
    }

    const int gu = tid & 63;           // gate-phase unit  (tid < 256)
    const int gb = tid >> 6;           // gate-phase batch (tid < 256)

    float* peer[CLUSTER];
#pragma unroll
    for (int r = 0; r < CLUSTER; r++)
        peer[r] = (float*)cl.map_shared_rank(hbuf, r);

    cl.sync();

    for (int t = 0; t < SEQ; t++) {
        const int cur = t & 1;
        const int nxt = cur ^ 1;

        // Prefetch gx (hidden under the dot loop)
        float gxr = 0.f, gxz = 0.f, gxn = 0.f;
        if (tid < 256) {
            const float* gp = g_gx + ((long)(B0 + gb) * SEQ + t) * G3 + (U0 + gu);
            gxr = gp[0]; gxz = gp[256]; gxn = gp[512];
        }

        // Dot: 32-long k-slice, 2 rows, 4 batches (batch-packed f32x2)
        const ulonglong2* hv2 =
            (const ulonglong2*)(hbuf + cur * HID * BPC) + c * KSL;
        unsigned long long aA0 = 0ull, aA1 = 0ull, aB0 = 0ull, aB1 = 0ull;
#pragma unroll
        for (int kp = 0; kp < KSL / 2; kp++) {
            float2 wb = *(const float2*)&wsB[2 * kp];
            ulonglong2 h0 = hv2[2 * kp];
            ulonglong2 h1 = hv2[2 * kp + 1];
            unsigned long long da0 = dup2(wa[2 * kp]);
            unsigned long long da1 = dup2(wa[2 * kp + 1]);
            unsigned long long db0 = dup2(wb.x);
            unsigned long long db1 = dup2(wb.y);
            fma2(aA0, da0, h0.x); fma2(aA1, da0, h0.y);
            fma2(aB0, db0, h0.x); fma2(aB1, db0, h0.y);
            fma2(aA0, da1, h1.x); fma2(aA1, da1, h1.y);
            fma2(aB0, db1, h1.x); fma2(aB1, db1, h1.y);
        }
        {
            float2 vA01 = unp2(aA0), vA23 = unp2(aA1);
            float2 vB01 = unp2(aB0), vB23 = unp2(aB1);
            const int pb = c * ROWS;
            part[0 * 1536 + pb + rA] = vA01.x;
            part[1 * 1536 + pb + rA] = vA01.y;
            part[2 * 1536 + pb + rA] = vA23.x;
            part[3 * 1536 + pb + rA] = vA23.y;
            part[0 * 1536 + pb + rB] = vB01.x;
            part[1 * 1536 + pb + rB] = vB01.y;
            part[2 * 1536 + pb + rB] = vB23.x;
            part[3 * 1536 + pb + rB] = vB23.y;
        }
        __syncthreads();

        if (tid < 256) {
            const float* pp = part + gb * 1536;
            float sr = bhs[gu], sz = bhs[64 + gu], sn = bhs[128 + gu];
#pragma unroll
            for (int cc = 0; cc < NSLC; cc++) {
                sr += pp[cc * ROWS + gu];
                sz += pp[cc * ROWS + 64 + gu];
                sn += pp[cc * ROWS + 128 + gu];
            }
            float r = __fdividef(1.0f, 1.0f + __expf(-(gxr + sr)));
            float z = __fdividef(1.0f, 1.0f + __expf(-(gxz + sz)));
            float narg = gxn + r * sn;
            float n = 2.0f * __fdividef(1.0f, 1.0f + __expf(-2.0f * narg)) - 1.0f;
            float hold = hbuf[cur * HID * BPC + (U0 + gu) * BPC + gb];
            float hnew = n + z * (hold - n);
            int off = nxt * HID * BPC + (U0 + gu) * BPC + gb;
#pragma unroll
            for (int r2 = 0; r2 < CLUSTER; r2++)
                peer[r2][off] = hnew;
        }
        cl.sync();   // release DSMEM stores; full cluster barrier
    }

    // Final h lives in buffer 0 (t=2047: nxt=0). Rank 0 emits out[b][2].
    if (rank == 0) {
        const int w = tid >> 5, lane = tid & 31;
        if (w < 8) {
            const int b = w >> 1, o = w & 1;
            float s = 0.f;
            for (int k = lane; k < HID; k += 32)
                s += hbuf[k * BPC + b] * __ldg(&Wfc[o * HID + k]);
#pragma unroll
            for (int d = 16; d > 0; d >>= 1)
                s += __shfl_xor_sync(0xFFFFFFFFu, s, d);
            if (lane == 0)
                out[(B0 + b) * 2 + o] = s + bfc[o];
        }
    }
}

// ---------------------------------------------------------------------------
extern "C" void kernel_launch(void* const* d_in, const int* in_sizes, int n_in,
                              void* d_out, int out_size) {
    const float* x   = (const float*)d_in[0];
    const float* Wx  = (const float*)d_in[1];
    const float* bx  = (const float*)d_in[2];
    const float* Wh  = (const float*)d_in[3];
    const float* bh  = (const float*)d_in[4];
    const float* Wfc = (const float*)d_in[5];
    const float* bfc = (const float*)d_in[6];
    float* out = (float*)d_out;

    cudaFuncSetAttribute(gx_gemm, cudaFuncAttributeMaxDynamicSharedMemorySize, GX_SMEM);
    cudaFuncSetAttribute(gru_rec, cudaFuncAttributeMaxDynamicSharedMemorySize, REC_SMEM);

    const int mtiles = (128 * SEQ) / GM;     // 2048
    const int ntiles = G3 / GN;              // 12
    gx_gemm<<<mtiles * ntiles, 256, GX_SMEM>>>(x, Wx, bx);
    gru_rec<<<32 * CLUSTER, NTHR, REC_SMEM>>>(Wh, bh, Wfc, bfc, out);
}